// round 2
// baseline (speedup 1.0000x reference)
#include <cuda_runtime.h>
#include <cuda_bf16.h>
#include <math.h>

// Fused Canny-magnitude pipeline for (16,3,512,512) fp32 input.
// One kernel: gray -> 5x5 separable Gaussian (reflect pad) -> Sobel (edge pad)
// -> magnitude -> directional NMS (zero pad) -> masked magnitude output.

#define TILE 32
#define GDIM 40   // gray tile  (halo 4)
#define BDIM 36   // blurred    (halo 2)
#define MDIM 34   // magnitude  (halo 1)
#define HW   512
#define AREA (512 * 512)

__device__ __forceinline__ int reflect_idx(int v) {
    // numpy 'reflect' for pad<=4 on size 512: -1->1, -2->2, 512->510, 513->509
    if (v < 0) v = -v;
    else if (v > HW - 1) v = 2 * (HW - 1) - v;
    return v;
}

__global__ __launch_bounds__(256, 4)
void canny_fused_kernel(const float* __restrict__ in, float* __restrict__ out) {
    __shared__ float gsm[GDIM][GDIM + 2];  // gray
    __shared__ float tsm[GDIM][BDIM + 2];  // horizontal blur
    __shared__ float bsm[BDIM][BDIM + 2];  // blurred (coords clamped per-axis)
    __shared__ float msm[MDIM][MDIM + 2];  // magnitude (0 outside image)

    const int tid = threadIdx.x;
    const int b   = blockIdx.z;
    const int by0 = blockIdx.y * TILE;
    const int bx0 = blockIdx.x * TILE;

    // Gaussian(5, sigma=1) weights
    const float wG[5] = {0.054488685f, 0.244201340f, 0.402619950f,
                         0.244201340f, 0.054488685f};

    const float* __restrict__ rp = in + (size_t)b * 3 * AREA;
    const float* __restrict__ gp = rp + AREA;
    const float* __restrict__ bp = rp + 2 * AREA;

    // ---- Stage 1: gray tile with reflect halo (radius 4) ----
    for (int i = tid; i < GDIM * GDIM; i += 256) {
        int r = i / GDIM, c = i % GDIM;
        int gr = reflect_idx(by0 + r - 4);
        int gc = reflect_idx(bx0 + c - 4);
        int off = gr * HW + gc;
        float xr = (rp[off] + 1.0f) * 0.5f;
        float xg = (gp[off] + 1.0f) * 0.5f;
        float xb = (bp[off] + 1.0f) * 0.5f;
        gsm[r][c] = 0.299f * xr + 0.587f * xg + 0.114f * xb;
    }
    __syncthreads();

    // ---- Stage 2: horizontal blur. Column coords are CLAMPED first (the
    // Sobel edge-pad applies to blurred coords), then reflect applies around
    // the clamped coordinate for the Gaussian taps. ----
    for (int i = tid; i < GDIM * BDIM; i += 256) {
        int r = i / BDIM, j = i % BDIM;
        int c  = bx0 + j - 2;
        int cc = min(max(c, 0), HW - 1);
        float s = 0.0f;
#pragma unroll
        for (int g = -2; g <= 2; g++) {
            int v = reflect_idx(cc + g);
            s += wG[g + 2] * gsm[r][v - (bx0 - 4)];
        }
        tsm[r][j] = s;
    }
    __syncthreads();

    // ---- Stage 3: vertical blur (row coords clamped, reflect taps) ----
    for (int i = tid; i < BDIM * BDIM; i += 256) {
        int jr = i / BDIM, jc = i % BDIM;
        int rr = by0 + jr - 2;
        int rc = min(max(rr, 0), HW - 1);
        float s = 0.0f;
#pragma unroll
        for (int g = -2; g <= 2; g++) {
            int v = reflect_idx(rc + g);
            s += wG[g + 2] * tsm[v - (by0 - 4)][jc];
        }
        bsm[jr][jc] = s;
    }
    __syncthreads();

    // ---- Stage 4: Sobel + magnitude (zero for out-of-image, matches the
    // NMS conv's zero padding) ----
    for (int i = tid; i < MDIM * MDIM; i += 256) {
        int ir = i / MDIM, ic = i % MDIM;
        int my = by0 + ir - 1, mx = bx0 + ic - 1;
        float m = 0.0f;
        if (my >= 0 && my < HW && mx >= 0 && mx < HW) {
            // blurred smem slot for coord c is c-(base-2); neighbors land at
            // [ir..ir+2][ic..ic+2] and already hold edge-clamped values.
            float b00 = bsm[ir][ic],     b01 = bsm[ir][ic + 1],     b02 = bsm[ir][ic + 2];
            float b10 = bsm[ir + 1][ic],                            b12 = bsm[ir + 1][ic + 2];
            float b20 = bsm[ir + 2][ic], b21 = bsm[ir + 2][ic + 1], b22 = bsm[ir + 2][ic + 2];
            float gx = (b02 - b00) + 2.0f * (b12 - b10) + (b22 - b20);
            float gy = (b20 - b00) + 2.0f * (b21 - b01) + (b22 - b02);
            m = sqrtf(gx * gx + gy * gy + 1e-6f);
        }
        msm[ir][ic] = m;
    }
    __syncthreads();

    // ---- Stage 5: NMS + output ----
    const int DY[8] = {0, -1, -1, -1, 0, 1, 1, 1};
    const int DX[8] = {1,  1,  0, -1, -1, -1, 0, 1};
    for (int i = tid; i < TILE * TILE; i += 256) {
        int iy = i / TILE, ix = i % TILE;
        int oy = by0 + iy, ox = bx0 + ix;

        float mc = msm[iy + 1][ix + 1];

        // recompute gx,gy at center for the angle (cheap smem reads)
        float b00 = bsm[iy + 1][ix + 1], b01 = bsm[iy + 1][ix + 2], b02 = bsm[iy + 1][ix + 3];
        float b10 = bsm[iy + 2][ix + 1],                            b12 = bsm[iy + 2][ix + 3];
        float b20 = bsm[iy + 3][ix + 1], b21 = bsm[iy + 3][ix + 2], b22 = bsm[iy + 3][ix + 3];
        float gx = (b02 - b00) + 2.0f * (b12 - b10) + (b22 - b20);
        float gy = (b20 - b00) + 2.0f * (b21 - b01) + (b22 - b02);

        // ang45 = round(deg(atan2)/45) = rint(atan2 * 4/pi); rint = half-even
        float a = rintf(atan2f(gy, gx) * 1.2732395447351628f);
        int ip = ((int)a + 8) & 7;
        int in_ = (ip + 4) & 7;

        float np_ = msm[iy + 1 + DY[ip]][ix + 1 + DX[ip]];
        float nn  = msm[iy + 1 + DY[in_]][ix + 1 + DX[in_]];
        float sel = fminf(mc - np_, mc - nn);

        out[(size_t)b * AREA + oy * HW + ox] = (sel > 0.0f) ? mc : 0.0f;
    }
}

extern "C" void kernel_launch(void* const* d_in, const int* in_sizes, int n_in,
                              void* d_out, int out_size) {
    const float* in = (const float*)d_in[0];
    float* out = (float*)d_out;
    dim3 grid(HW / TILE, HW / TILE, 16);  // 16x16 tiles x 16 images
    canny_fused_kernel<<<grid, 256>>>(in, out);
}

// round 5
// speedup vs baseline: 1.2894x; 1.2894x over previous
#include <cuda_runtime.h>
#include <math.h>

// Fused Canny-magnitude, (16,3,512,512) fp32 -> (16,1,512,512) fp32.
// 32x8 thread layout, constant-offset addressing, no div/mod, no atan2f.

#define TILE 32
#define GDIM 40   // gray tile   (halo 4)
#define BDIM 36   // blurred     (halo 2)
#define MDIM 34   // magnitude   (halo 1)
#define HW   512
#define AREA (HW * HW)

__device__ __forceinline__ int reflect_idx(int v) {
    // numpy 'reflect' for |pad|<=4 on size 512
    if (v < 0) v = -v;
    else if (v > HW - 1) v = 2 * (HW - 1) - v;
    return v;
}

__global__ __launch_bounds__(256, 4)
void canny_fused_kernel(const float* __restrict__ in, float* __restrict__ out) {
    __shared__ float gsm[GDIM][GDIM + 2];  // gray        (reused as gx in stage 4/5)
    __shared__ float tsm[GDIM][BDIM + 2];  // horiz blur  (reused as gy in stage 4/5)
    __shared__ float bsm[BDIM][BDIM + 2];  // blurred
    __shared__ float msm[MDIM][MDIM + 2];  // magnitude (0 outside image)

    const int tid = threadIdx.x;
    const int tx  = tid & 31;
    const int ty  = tid >> 5;
    const int b   = blockIdx.z;
    const int by0 = blockIdx.y * TILE;
    const int bx0 = blockIdx.x * TILE;

    const float w0 = 0.054488685f, w1 = 0.244201340f, w2 = 0.402619950f;

    const float* __restrict__ rp  = in + (size_t)b * 3 * AREA;
    const float* __restrict__ gp  = rp + AREA;
    const float* __restrict__ bp2 = rp + 2 * AREA;

    // ---- Stage 1: gray 40x40 with reflect halo ----
    {
        const int  gc0  = reflect_idx(bx0 + tx - 4);
        const int  gc1  = reflect_idx(bx0 + tx + 28);
        const bool has2 = (tx < 8);
#pragma unroll
        for (int k = 0; k < 5; k++) {
            const int r  = ty + 8 * k;
            const int ro = reflect_idx(by0 + r - 4) * HW;
            {
                float xr = (rp [ro + gc0] + 1.0f) * 0.5f;
                float xg = (gp [ro + gc0] + 1.0f) * 0.5f;
                float xb = (bp2[ro + gc0] + 1.0f) * 0.5f;
                gsm[r][tx] = 0.299f * xr + 0.587f * xg + 0.114f * xb;
            }
            if (has2) {
                float xr = (rp [ro + gc1] + 1.0f) * 0.5f;
                float xg = (gp [ro + gc1] + 1.0f) * 0.5f;
                float xb = (bp2[ro + gc1] + 1.0f) * 0.5f;
                gsm[r][tx + 32] = 0.299f * xr + 0.587f * xg + 0.114f * xb;
            }
        }
    }
    __syncthreads();

    // ---- Stage 2: horizontal blur -> tsm[40][36]. Column coord is clamped
    // (Sobel edge-pad on blurred coords), then reflect around it for taps.
    // Slots hoisted: computed once per thread, reused over 5 rows. ----
    {
        int s0[5];
        {
            const int cc = min(max(bx0 + tx - 2, 0), HW - 1);
#pragma unroll
            for (int g = 0; g < 5; g++) s0[g] = reflect_idx(cc + g - 2) - (bx0 - 4);
        }
        const bool has2 = (tx < 4);
        int s1[5];
        if (has2) {
            const int cc = min(max(bx0 + tx + 30, 0), HW - 1);
#pragma unroll
            for (int g = 0; g < 5; g++) s1[g] = reflect_idx(cc + g - 2) - (bx0 - 4);
        }
#pragma unroll
        for (int k = 0; k < 5; k++) {
            const int r = ty + 8 * k;
            {
                float s = w0 * gsm[r][s0[0]];
                s += w1 * gsm[r][s0[1]];
                s += w2 * gsm[r][s0[2]];
                s += w1 * gsm[r][s0[3]];
                s += w0 * gsm[r][s0[4]];
                tsm[r][tx] = s;
            }
            if (has2) {
                float s = w0 * gsm[r][s1[0]];
                s += w1 * gsm[r][s1[1]];
                s += w2 * gsm[r][s1[2]];
                s += w1 * gsm[r][s1[3]];
                s += w0 * gsm[r][s1[4]];
                tsm[r][tx + 32] = s;
            }
        }
    }
    __syncthreads();

    // ---- Stage 3: vertical blur -> bsm[36][36] (row clamped, reflect taps) ----
    {
        const bool has2 = (tx < 4);
#pragma unroll
        for (int k = 0; k < 5; k++) {
            const int jr = ty + 8 * k;
            if (jr < BDIM) {
                const int rc = min(max(by0 + jr - 2, 0), HW - 1);
                const int r0 = reflect_idx(rc - 2) - (by0 - 4);
                const int r1 = reflect_idx(rc - 1) - (by0 - 4);
                const int r2 = reflect_idx(rc    ) - (by0 - 4);
                const int r3 = reflect_idx(rc + 1) - (by0 - 4);
                const int r4 = reflect_idx(rc + 2) - (by0 - 4);
                {
                    float s = w0 * tsm[r0][tx];
                    s += w1 * tsm[r1][tx];
                    s += w2 * tsm[r2][tx];
                    s += w1 * tsm[r3][tx];
                    s += w0 * tsm[r4][tx];
                    bsm[jr][tx] = s;
                }
                if (has2) {
                    float s = w0 * tsm[r0][tx + 32];
                    s += w1 * tsm[r1][tx + 32];
                    s += w2 * tsm[r2][tx + 32];
                    s += w1 * tsm[r3][tx + 32];
                    s += w0 * tsm[r4][tx + 32];
                    bsm[jr][tx + 32] = s;
                }
            }
        }
    }
    __syncthreads();

    // gsm/tsm are dead now; reuse their storage for gx/gy (34x36 fits in both).
    float (*gxs)[MDIM + 2] = (float (*)[MDIM + 2])gsm;
    float (*gys)[MDIM + 2] = (float (*)[MDIM + 2])tsm;

    // ---- Stage 4: Sobel + magnitude -> msm/gxs/gys [34][34] ----
    {
        const bool has2 = (tx < 2);
#pragma unroll
        for (int k = 0; k < 5; k++) {
            const int ir = ty + 8 * k;
            if (ir < MDIM) {
                const int  my    = by0 + ir - 1;
                const bool rowok = (my >= 0) && (my < HW);
#pragma unroll
                for (int cpass = 0; cpass < 2; cpass++) {
                    if (cpass == 1 && !has2) break;
                    const int ic = tx + cpass * 32;
                    const int mx = bx0 + ic - 1;
                    float m = 0.0f, gx = 0.0f, gy = 0.0f;
                    if (rowok && mx >= 0 && mx < HW) {
                        float b00 = bsm[ir][ic],     b01 = bsm[ir][ic + 1],     b02 = bsm[ir][ic + 2];
                        float b10 = bsm[ir + 1][ic],                            b12 = bsm[ir + 1][ic + 2];
                        float b20 = bsm[ir + 2][ic], b21 = bsm[ir + 2][ic + 1], b22 = bsm[ir + 2][ic + 2];
                        gx = (b02 - b00) + 2.0f * (b12 - b10) + (b22 - b20);
                        gy = (b20 - b00) + 2.0f * (b21 - b01) + (b22 - b02);
                        m  = sqrtf(gx * gx + gy * gy + 1e-6f);
                    }
                    msm[ir][ic] = m;
                    gxs[ir][ic] = gx;
                    gys[ir][ic] = gy;
                }
            }
        }
    }
    __syncthreads();

    // ---- Stage 5: octant NMS + output. Only idx mod 4 matters (min over the
    // idx/idx+4 neighbor pair), decided by tan(22.5deg) comparisons. ----
    {
        const float T = 0.41421356237f;  // tan(22.5 deg)
        float* __restrict__ op = out + (size_t)b * AREA + (size_t)by0 * HW + bx0;
#pragma unroll
        for (int k = 0; k < 4; k++) {
            const int iy = ty + 8 * k;
            const float mc = msm[iy + 1][tx + 1];
            const float gx = gxs[iy + 1][tx + 1];
            const float gy = gys[iy + 1][tx + 1];
            const float ax = fabsf(gx), ay = fabsf(gy);
            int dy, dx;
            if (ay <= T * ax)                    { dy = 0;  dx = 1; }  // horizontal
            else if (ax <= T * ay)               { dy = 1;  dx = 0; }  // vertical
            else if ((gx < 0.0f) == (gy < 0.0f)) { dy = -1; dx = 1; }  // 45/225 pair
            else                                 { dy = 1;  dx = 1; }  // 135/315 pair
            const float n1 = msm[iy + 1 + dy][tx + 1 + dx];
            const float n2 = msm[iy + 1 - dy][tx + 1 - dx];
            const float sel = fminf(mc - n1, mc - n2);
            op[(size_t)iy * HW + tx] = (sel > 0.0f) ? mc : 0.0f;
        }
    }
}

extern "C" void kernel_launch(void* const* d_in, const int* in_sizes, int n_in,
                              void* d_out, int out_size) {
    const float* in = (const float*)d_in[0];
    float* out = (float*)d_out;
    dim3 grid(HW / TILE, HW / TILE, 16);
    canny_fused_kernel<<<grid, 256>>>(in, out);
}